// round 5
// baseline (speedup 1.0000x reference)
#include <cuda_runtime.h>
#include <cuda_bf16.h>
#include <cstdint>

#define N_NODES 50000
#define N_EDGES 800000
#define CAP 64

// ---------------- scratch (device globals; no allocation allowed) ----------
__device__ int   g_count[N_NODES];
__device__ int   g_slot[N_NODES * CAP];
__device__ float g_z[N_NODES * 128];
__device__ float g_h[N_NODES * 128];
// packed split weights, one uint4 per (n, ks, wkp):
//   .x = hi{W[n][k0],W[n][k0+1]}  .y = hi{W[n][k0+8],W[n][k0+9]}
//   .z = lo{...k0...}             .w = lo{...k0+8...}
// where k0 = (ks*8 + wkp)*2.  W1: 4096 | W2: 4096 | W3: 2048
__device__ uint4 g_wq[10240];

// ---------------- small helpers ----------------
__device__ __forceinline__ uint32_t smem_u32(const void* p) {
    uint32_t a;
    asm("{ .reg .u64 t; cvta.to.shared.u64 t, %1; cvt.u32.u64 %0, t; }"
        : "=r"(a) : "l"(p));
    return a;
}

#define LDMATRIX_X4(r, addr) \
    asm volatile("ldmatrix.sync.aligned.m8n8.x4.shared.b16 {%0,%1,%2,%3}, [%4];" \
                 : "=r"((r)[0]), "=r"((r)[1]), "=r"((r)[2]), "=r"((r)[3]) \
                 : "r"(addr))

#define MMA_BF16(acc, a, b0, b1) \
    asm volatile("mma.sync.aligned.m16n8k16.row.col.f32.bf16.bf16.f32 " \
                 "{%0,%1,%2,%3}, {%4,%5,%6,%7}, {%8,%9}, {%0,%1,%2,%3};" \
                 : "+f"((acc)[0]), "+f"((acc)[1]), "+f"((acc)[2]), "+f"((acc)[3]) \
                 : "r"((a)[0]), "r"((a)[1]), "r"((a)[2]), "r"((a)[3]), \
                   "r"(b0), "r"(b1))

__device__ __forceinline__ uint32_t pack_bf162(float a, float b) {
    __nv_bfloat162 p;
    p.x = __float2bfloat16_rn(a);
    p.y = __float2bfloat16_rn(b);
    return *reinterpret_cast<uint32_t*>(&p);
}

__device__ __forceinline__ uint32_t hi_bf162(float a, float b) {
    __nv_bfloat162 p;
    p.x = __float2bfloat16_rn(a);
    p.y = __float2bfloat16_rn(b);
    return *reinterpret_cast<uint32_t*>(&p);
}

// ---------------- setup: zero degree counters + build packed split-W -------
__global__ void setup_kernel(const float* __restrict__ W1,
                             const float* __restrict__ W2,
                             const float* __restrict__ W3) {
    int i = blockIdx.x * blockDim.x + threadIdx.x;
    if (i < N_NODES) g_count[i] = 0;
    if (i < 10240) {
        const float* W;
        int rel;
        if (i < 4096)      { W = W1; rel = i; }
        else if (i < 8192) { W = W2; rel = i - 4096; }
        else               { W = W3; rel = i - 8192; }
        int n  = rel >> 5;            // 32 uint4 per row
        int q  = rel & 31;
        int ks  = q >> 2;
        int wkp = q & 3;
        int k0 = (ks * 8 + wkp) * 2;
        const float* wr = W + n * 128;
        float a0 = wr[k0],     a1 = wr[k0 + 1];
        float b0 = wr[k0 + 8], b1 = wr[k0 + 9];
        __nv_bfloat16 ha0 = __float2bfloat16_rn(a0);
        __nv_bfloat16 ha1 = __float2bfloat16_rn(a1);
        __nv_bfloat16 hb0 = __float2bfloat16_rn(b0);
        __nv_bfloat16 hb1 = __float2bfloat16_rn(b1);
        uint4 o;
        __nv_bfloat162 ph; ph.x = ha0; ph.y = ha1;
        o.x = *reinterpret_cast<uint32_t*>(&ph);
        __nv_bfloat162 qh; qh.x = hb0; qh.y = hb1;
        o.y = *reinterpret_cast<uint32_t*>(&qh);
        o.z = pack_bf162(a0 - __bfloat162float(ha0), a1 - __bfloat162float(ha1));
        o.w = pack_bf162(b0 - __bfloat162float(hb0), b1 - __bfloat162float(hb1));
        g_wq[i] = o;
    }
}

// ---------------- bucket adjacency build ----------------
__global__ void fill_kernel(const int* __restrict__ src,
                            const int* __restrict__ dst) {
    int e = blockIdx.x * blockDim.x + threadIdx.x;
    if (e < N_EDGES) {
        int d = dst[e];
        int p = atomicAdd(&g_count[d], 1);
        if (p < CAP) g_slot[d * CAP + p] = src[e];
    }
}

// ---------------- mma.sync split-bf16 GEMM: Z[128-tile][N] = A @ W^T -------
// A: [N_NODES,128] fp32 row-major; split to bf16 hi/lo during smem staging.
// Wq: packed split weights (uint4 per thread-fragment).
// D = Ahi*Whi^T + Ahi*Wlo^T + Alo*Whi^T (fp32 acc).
template <int N>
__global__ void __launch_bounds__(128, 2) mma_gemm(
    const float* __restrict__ A, const uint4* __restrict__ Wq,
    float* __restrict__ Z) {
    constexpr int NT  = N / 8;       // n-tiles of 8
    constexpr int LDA = 136;         // padded row stride (bf16 elems)

    extern __shared__ __nv_bfloat16 smem[];
    __nv_bfloat16* Ash = smem;              // [128][LDA] hi
    __nv_bfloat16* Asl = smem + 128 * LDA;  // [128][LDA] lo

    const int tid  = threadIdx.x;
    const int wid  = tid >> 5;
    const int lane = tid & 31;
    const int m0   = blockIdx.x * 128;

    // stage A tile: load fp32, split into hi/lo bf16 smem tiles
    for (int t = tid; t < 4096; t += 128) {
        int r = t >> 5;
        int c = (t & 31) << 2;
        int m = m0 + r;
        float4 v = make_float4(0.f, 0.f, 0.f, 0.f);
        if (m < N_NODES)
            v = *reinterpret_cast<const float4*>(A + (size_t)m * 128 + c);
        __nv_bfloat16 h0 = __float2bfloat16_rn(v.x);
        __nv_bfloat16 h1 = __float2bfloat16_rn(v.y);
        __nv_bfloat16 h2 = __float2bfloat16_rn(v.z);
        __nv_bfloat16 h3 = __float2bfloat16_rn(v.w);
        __nv_bfloat162 hp0; hp0.x = h0; hp0.y = h1;
        __nv_bfloat162 hp1; hp1.x = h2; hp1.y = h3;
        uint2 hv, lv;
        hv.x = *reinterpret_cast<uint32_t*>(&hp0);
        hv.y = *reinterpret_cast<uint32_t*>(&hp1);
        lv.x = pack_bf162(v.x - __bfloat162float(h0), v.y - __bfloat162float(h1));
        lv.y = pack_bf162(v.z - __bfloat162float(h2), v.w - __bfloat162float(h3));
        *reinterpret_cast<uint2*>(Ash + r * LDA + c) = hv;
        *reinterpret_cast<uint2*>(Asl + r * LDA + c) = lv;
    }
    __syncthreads();

    float acc[2][NT][4];
    #pragma unroll
    for (int mt = 0; mt < 2; mt++)
        #pragma unroll
        for (int nt = 0; nt < NT; nt++)
            #pragma unroll
            for (int i = 0; i < 4; i++) acc[mt][nt][i] = 0.0f;

    const int wrow = wid * 32;
    const int lrow = lane & 15;
    const int kgrp = (lane >> 4) * 8;
    const int wn   = lane >> 2;       // B-frag row within n8 tile
    const int wkp  = lane & 3;        // k-pair index within k8 group

    #pragma unroll
    for (int ks = 0; ks < 8; ks++) {
        const int k0 = ks * 16;
        uint32_t ah[2][4], al[2][4];
        #pragma unroll
        for (int mt = 0; mt < 2; mt++) {
            uint32_t ad = smem_u32(Ash + (wrow + mt * 16 + lrow) * LDA + k0 + kgrp);
            LDMATRIX_X4(ah[mt], ad);
            uint32_t bd = smem_u32(Asl + (wrow + mt * 16 + lrow) * LDA + k0 + kgrp);
            LDMATRIX_X4(al[mt], bd);
        }
        #pragma unroll
        for (int nt = 0; nt < NT; nt++) {
            uint4 q = Wq[(size_t)(nt * 8 + wn) * 32 + ks * 4 + wkp];
            #pragma unroll
            for (int mt = 0; mt < 2; mt++) {
                MMA_BF16(acc[mt][nt], ah[mt], q.x, q.y);
                MMA_BF16(acc[mt][nt], ah[mt], q.z, q.w);
                MMA_BF16(acc[mt][nt], al[mt], q.x, q.y);
            }
        }
    }

    // epilogue: c0,c1 -> row lane/4, cols 2*(lane%4); c2,c3 -> row+8
    #pragma unroll
    for (int mt = 0; mt < 2; mt++) {
        int r0 = m0 + wrow + mt * 16 + (lane >> 2);
        #pragma unroll
        for (int nt = 0; nt < NT; nt++) {
            int col = nt * 8 + (lane & 3) * 2;
            if (r0 < N_NODES)
                *reinterpret_cast<float2*>(Z + (size_t)r0 * N + col) =
                    make_float2(acc[mt][nt][0], acc[mt][nt][1]);
            if (r0 + 8 < N_NODES)
                *reinterpret_cast<float2*>(Z + (size_t)(r0 + 8) * N + col) =
                    make_float2(acc[mt][nt][2], acc[mt][nt][3]);
        }
    }
}

// ---------------- gather + self + inv-scale + relu ----------------
// Indices distributed across lanes, broadcast via shfl: no memory loads on
// the gather critical path -> high MLP.
__global__ void agg128_kernel(const float* __restrict__ Z,
                              float* __restrict__ H) {
    int node = (blockIdx.x * blockDim.x + threadIdx.x) >> 5;
    if (node >= N_NODES) return;
    int lane = threadIdx.x & 31;
    const float4* Zv = reinterpret_cast<const float4*>(Z);
    float4 acc = Zv[node * 32 + lane];
    int cnt = g_count[node];
    int deg = cnt < CAP ? cnt : CAP;
    const int* sl = &g_slot[node * CAP];
    int idx0 = (lane < deg)      ? sl[lane]      : 0;
    int idx1 = (32 + lane < deg) ? sl[32 + lane] : 0;

    float4 a1 = make_float4(0.f, 0.f, 0.f, 0.f);
    int n0 = deg < 32 ? deg : 32;
    int j = 0;
    for (; j + 2 <= n0; j += 2) {
        int s0 = __shfl_sync(0xffffffffu, idx0, j);
        int s1 = __shfl_sync(0xffffffffu, idx0, j + 1);
        float4 v0 = Zv[s0 * 32 + lane];
        float4 v1 = Zv[s1 * 32 + lane];
        acc.x += v0.x; acc.y += v0.y; acc.z += v0.z; acc.w += v0.w;
        a1.x  += v1.x; a1.y  += v1.y; a1.z  += v1.z; a1.w  += v1.w;
    }
    if (j < n0) {
        int s0 = __shfl_sync(0xffffffffu, idx0, j);
        float4 v0 = Zv[s0 * 32 + lane];
        acc.x += v0.x; acc.y += v0.y; acc.z += v0.z; acc.w += v0.w;
    }
    for (j = 32; j + 2 <= deg; j += 2) {
        int s0 = __shfl_sync(0xffffffffu, idx1, j - 32);
        int s1 = __shfl_sync(0xffffffffu, idx1, j - 31);
        float4 v0 = Zv[s0 * 32 + lane];
        float4 v1 = Zv[s1 * 32 + lane];
        acc.x += v0.x; acc.y += v0.y; acc.z += v0.z; acc.w += v0.w;
        a1.x  += v1.x; a1.y  += v1.y; a1.z  += v1.z; a1.w  += v1.w;
    }
    if (j < deg) {
        int s0 = __shfl_sync(0xffffffffu, idx1, j - 32);
        float4 v0 = Zv[s0 * 32 + lane];
        acc.x += v0.x; acc.y += v0.y; acc.z += v0.z; acc.w += v0.w;
    }
    acc.x += a1.x; acc.y += a1.y; acc.z += a1.z; acc.w += a1.w;

    float sc = 1.0f / ((float)cnt + 1.0f);
    float4 o = make_float4(fmaxf(acc.x * sc, 0.f), fmaxf(acc.y * sc, 0.f),
                           fmaxf(acc.z * sc, 0.f), fmaxf(acc.w * sc, 0.f));
    reinterpret_cast<float4*>(H)[node * 32 + lane] = o;
}

// Final layer: 64-dim, fp32 output.
__global__ void agg64_kernel(const float* __restrict__ Z,
                             float* __restrict__ out) {
    int node = (blockIdx.x * blockDim.x + threadIdx.x) >> 5;
    if (node >= N_NODES) return;
    int lane = threadIdx.x & 31;
    const float2* Zv = reinterpret_cast<const float2*>(Z);
    float2 acc = Zv[node * 32 + lane];
    int cnt = g_count[node];
    int deg = cnt < CAP ? cnt : CAP;
    const int* sl = &g_slot[node * CAP];
    int idx0 = (lane < deg)      ? sl[lane]      : 0;
    int idx1 = (32 + lane < deg) ? sl[32 + lane] : 0;

    float2 a1 = make_float2(0.f, 0.f);
    int n0 = deg < 32 ? deg : 32;
    int j = 0;
    for (; j + 2 <= n0; j += 2) {
        int s0 = __shfl_sync(0xffffffffu, idx0, j);
        int s1 = __shfl_sync(0xffffffffu, idx0, j + 1);
        float2 v0 = Zv[s0 * 32 + lane];
        float2 v1 = Zv[s1 * 32 + lane];
        acc.x += v0.x; acc.y += v0.y;
        a1.x  += v1.x; a1.y  += v1.y;
    }
    if (j < n0) {
        int s0 = __shfl_sync(0xffffffffu, idx0, j);
        float2 v0 = Zv[s0 * 32 + lane];
        acc.x += v0.x; acc.y += v0.y;
    }
    for (j = 32; j + 2 <= deg; j += 2) {
        int s0 = __shfl_sync(0xffffffffu, idx1, j - 32);
        int s1 = __shfl_sync(0xffffffffu, idx1, j - 31);
        float2 v0 = Zv[s0 * 32 + lane];
        float2 v1 = Zv[s1 * 32 + lane];
        acc.x += v0.x; acc.y += v0.y;
        a1.x  += v1.x; a1.y  += v1.y;
    }
    if (j < deg) {
        int s0 = __shfl_sync(0xffffffffu, idx1, j - 32);
        float2 v0 = Zv[s0 * 32 + lane];
        acc.x += v0.x; acc.y += v0.y;
    }
    acc.x += a1.x; acc.y += a1.y;

    float sc = 1.0f / ((float)cnt + 1.0f);
    float2 o = make_float2(fmaxf(acc.x * sc, 0.f), fmaxf(acc.y * sc, 0.f));
    reinterpret_cast<float2*>(out)[node * 32 + lane] = o;
}

// ---------------- launch ----------------
extern "C" void kernel_launch(void* const* d_in, const int* in_sizes, int n_in,
                              void* d_out, int out_size) {
    const float* x   = (const float*)d_in[0];
    const int*   ei  = (const int*)d_in[1];
    const float* W1  = (const float*)d_in[2];
    const float* W2  = (const float*)d_in[3];
    const float* W3  = (const float*)d_in[4];
    float*       out = (float*)d_out;

    const int* src = ei;
    const int* dst = ei + N_EDGES;

    float* z  = nullptr;
    float* h  = nullptr;
    uint4* wq = nullptr;
    cudaGetSymbolAddress((void**)&z,  g_z);
    cudaGetSymbolAddress((void**)&h,  g_h);
    cudaGetSymbolAddress((void**)&wq, g_wq);

    constexpr int SMEM_A = 2 * 128 * 136 * 2;   // 69632 bytes
    cudaFuncSetAttribute(mma_gemm<128>, cudaFuncAttributeMaxDynamicSharedMemorySize, SMEM_A);
    cudaFuncSetAttribute(mma_gemm<64>,  cudaFuncAttributeMaxDynamicSharedMemorySize, SMEM_A);

    const int TPB = 256;
    const int gemm_blocks = (N_NODES + 127) / 128;           // 391
    const int agg_blocks  = (N_NODES * 32 + TPB - 1) / TPB;  // 6250

    // setup (zero counters + split/pack weights), adjacency buckets
    setup_kernel<<<(N_NODES + TPB - 1) / TPB, TPB>>>(W1, W2, W3);
    fill_kernel<<<(N_EDGES + TPB - 1) / TPB, TPB>>>(src, dst);

    // layer 1
    mma_gemm<128><<<gemm_blocks, 128, SMEM_A>>>(x, wq, z);
    agg128_kernel<<<agg_blocks, TPB>>>(z, h);
    // layer 2
    mma_gemm<128><<<gemm_blocks, 128, SMEM_A>>>(h, wq + 4096, z);
    agg128_kernel<<<agg_blocks, TPB>>>(z, h);
    // layer 3 (N=64), final relu + write out
    mma_gemm<64><<<gemm_blocks, 128, SMEM_A>>>(h, wq + 8192, z);
    agg64_kernel<<<agg_blocks, TPB>>>(z, out);
}

// round 6
// speedup vs baseline: 1.2247x; 1.2247x over previous
#include <cuda_runtime.h>
#include <cuda_bf16.h>
#include <cstdint>

#define N_NODES 50000
#define N_EDGES 800000
#define CAP 64

// ---------------- scratch (device globals; no allocation allowed) ----------
__device__ int   g_count[N_NODES];
__device__ int   g_slot[N_NODES * CAP];
__device__ float g_z[N_NODES * 128];
__device__ float g_h[N_NODES * 128];
// packed split weights: per (n, k-pair): {hi[k],hi[k+1]} , {lo[k],lo[k+1]}
// W1: 8192 uint2 | W2: 8192 | W3: 4096
__device__ uint2 g_wp[20480];

// ---------------- small helpers ----------------
__device__ __forceinline__ uint32_t smem_u32(const void* p) {
    uint32_t a;
    asm("{ .reg .u64 t; cvta.to.shared.u64 t, %1; cvt.u32.u64 %0, t; }"
        : "=r"(a) : "l"(p));
    return a;
}

#define LDMATRIX_X4(r, addr) \
    asm volatile("ldmatrix.sync.aligned.m8n8.x4.shared.b16 {%0,%1,%2,%3}, [%4];" \
                 : "=r"((r)[0]), "=r"((r)[1]), "=r"((r)[2]), "=r"((r)[3]) \
                 : "r"(addr))

#define MMA_BF16(acc, a, b0, b1) \
    asm volatile("mma.sync.aligned.m16n8k16.row.col.f32.bf16.bf16.f32 " \
                 "{%0,%1,%2,%3}, {%4,%5,%6,%7}, {%8,%9}, {%0,%1,%2,%3};" \
                 : "+f"((acc)[0]), "+f"((acc)[1]), "+f"((acc)[2]), "+f"((acc)[3]) \
                 : "r"((a)[0]), "r"((a)[1]), "r"((a)[2]), "r"((a)[3]), \
                   "r"(b0), "r"(b1))

__device__ __forceinline__ uint32_t pack_bf162(float a, float b) {
    __nv_bfloat162 p;
    p.x = __float2bfloat16_rn(a);
    p.y = __float2bfloat16_rn(b);
    return *reinterpret_cast<uint32_t*>(&p);
}

// ---------------- setup: zero degree counters + build packed split-W -------
__global__ void setup_kernel(const float* __restrict__ W1,
                             const float* __restrict__ W2,
                             const float* __restrict__ W3) {
    int i = blockIdx.x * blockDim.x + threadIdx.x;
    if (i < N_NODES) g_count[i] = 0;
    if (i < 20480) {
        const float* W;
        int rel;
        int ld = 128;
        if (i < 8192)       { W = W1; rel = i; }
        else if (i < 16384) { W = W2; rel = i - 8192; }
        else                { W = W3; rel = i - 16384; }
        int n  = rel >> 6;
        int kp = rel & 63;
        float v0 = W[n * ld + kp * 2 + 0];
        float v1 = W[n * ld + kp * 2 + 1];
        __nv_bfloat16 h0 = __float2bfloat16_rn(v0);
        __nv_bfloat16 h1 = __float2bfloat16_rn(v1);
        float l0 = v0 - __bfloat162float(h0);
        float l1 = v1 - __bfloat162float(h1);
        __nv_bfloat162 hi; hi.x = h0; hi.y = h1;
        uint2 out;
        out.x = *reinterpret_cast<uint32_t*>(&hi);
        out.y = pack_bf162(l0, l1);
        g_wp[i] = out;
    }
}

// ---------------- bucket adjacency build ----------------
__global__ void fill_kernel(const int* __restrict__ src,
                            const int* __restrict__ dst) {
    int e = blockIdx.x * blockDim.x + threadIdx.x;
    if (e < N_EDGES) {
        int d = dst[e];
        int p = atomicAdd(&g_count[d], 1);
        if (p < CAP) g_slot[d * CAP + p] = src[e];
    }
}

// ---------------- mma.sync split-bf16 GEMM: Z[128-tile][N] = A @ W^T -------
// A: [N_NODES,128] fp32 row-major; split to bf16 hi/lo during smem staging.
// Wp: packed split weights. D = Ahi*Whi^T + Ahi*Wlo^T + Alo*Whi^T (fp32 acc).
// 128 threads = 4 warps; warp w owns rows [w*32, w*32+32) (2 m16 tiles).
template <int N>
__global__ void __launch_bounds__(128, 2) mma_gemm(
    const float* __restrict__ A, const uint2* __restrict__ Wp,
    float* __restrict__ Z) {
    constexpr int NT  = N / 8;       // n-tiles of 8
    constexpr int LDA = 136;         // padded row stride (bf16 elems)

    extern __shared__ __nv_bfloat16 smem[];
    __nv_bfloat16* Ash = smem;              // [128][LDA] hi
    __nv_bfloat16* Asl = smem + 128 * LDA;  // [128][LDA] lo

    const int tid  = threadIdx.x;
    const int wid  = tid >> 5;
    const int lane = tid & 31;
    const int m0   = blockIdx.x * 128;

    // stage A tile: load fp32, split into hi/lo bf16 smem tiles
    for (int t = tid; t < 4096; t += 128) {
        int r = t >> 5;
        int c = (t & 31) << 2;
        int m = m0 + r;
        float4 v = make_float4(0.f, 0.f, 0.f, 0.f);
        if (m < N_NODES)
            v = *reinterpret_cast<const float4*>(A + (size_t)m * 128 + c);
        __nv_bfloat16 h0 = __float2bfloat16_rn(v.x);
        __nv_bfloat16 h1 = __float2bfloat16_rn(v.y);
        __nv_bfloat16 h2 = __float2bfloat16_rn(v.z);
        __nv_bfloat16 h3 = __float2bfloat16_rn(v.w);
        __nv_bfloat162 hp0; hp0.x = h0; hp0.y = h1;
        __nv_bfloat162 hp1; hp1.x = h2; hp1.y = h3;
        uint2 hv, lv;
        hv.x = *reinterpret_cast<uint32_t*>(&hp0);
        hv.y = *reinterpret_cast<uint32_t*>(&hp1);
        lv.x = pack_bf162(v.x - __bfloat162float(h0), v.y - __bfloat162float(h1));
        lv.y = pack_bf162(v.z - __bfloat162float(h2), v.w - __bfloat162float(h3));
        *reinterpret_cast<uint2*>(Ash + r * LDA + c) = hv;
        *reinterpret_cast<uint2*>(Asl + r * LDA + c) = lv;
    }
    __syncthreads();

    float acc[2][NT][4];
    #pragma unroll
    for (int mt = 0; mt < 2; mt++)
        #pragma unroll
        for (int nt = 0; nt < NT; nt++)
            #pragma unroll
            for (int i = 0; i < 4; i++) acc[mt][nt][i] = 0.0f;

    const int wrow = wid * 32;
    const int lrow = lane & 15;
    const int kgrp = (lane >> 4) * 8;
    const int wn   = lane >> 2;       // B-frag row within n8 tile
    const int wkp  = lane & 3;        // k-pair index within k8 group

    #pragma unroll
    for (int ks = 0; ks < 8; ks++) {
        const int k0 = ks * 16;
        uint32_t ah[2][4], al[2][4];
        #pragma unroll
        for (int mt = 0; mt < 2; mt++) {
            uint32_t ad = smem_u32(Ash + (wrow + mt * 16 + lrow) * LDA + k0 + kgrp);
            LDMATRIX_X4(ah[mt], ad);
            uint32_t bd = smem_u32(Asl + (wrow + mt * 16 + lrow) * LDA + k0 + kgrp);
            LDMATRIX_X4(al[mt], bd);
        }
        #pragma unroll
        for (int nt = 0; nt < NT; nt++) {
            // packed W: row n = nt*8+wn, k pairs (k0/2 + wkp) and (+4)
            const uint2* wp = Wp + (size_t)(nt * 8 + wn) * 64 + (k0 >> 1) + wkp;
            uint2 p0 = wp[0];
            uint2 p1 = wp[4];
            #pragma unroll
            for (int mt = 0; mt < 2; mt++) {
                MMA_BF16(acc[mt][nt], ah[mt], p0.x, p1.x);
                MMA_BF16(acc[mt][nt], ah[mt], p0.y, p1.y);
                MMA_BF16(acc[mt][nt], al[mt], p0.x, p1.x);
            }
        }
    }

    // epilogue: c0,c1 -> row lane/4, cols 2*(lane%4); c2,c3 -> row+8
    #pragma unroll
    for (int mt = 0; mt < 2; mt++) {
        int r0 = m0 + wrow + mt * 16 + (lane >> 2);
        #pragma unroll
        for (int nt = 0; nt < NT; nt++) {
            int col = nt * 8 + (lane & 3) * 2;
            if (r0 < N_NODES)
                *reinterpret_cast<float2*>(Z + (size_t)r0 * N + col) =
                    make_float2(acc[mt][nt][0], acc[mt][nt][1]);
            if (r0 + 8 < N_NODES)
                *reinterpret_cast<float2*>(Z + (size_t)(r0 + 8) * N + col) =
                    make_float2(acc[mt][nt][2], acc[mt][nt][3]);
        }
    }
}

// ---------------- gather + self + inv-scale + relu ----------------
// Index quads loaded as int4 with one-quad-ahead software pipelining: the
// next quad's index fetch overlaps the current quad's gathers.
__global__ void agg128_kernel(const float* __restrict__ Z,
                              float* __restrict__ H) {
    int node = (blockIdx.x * blockDim.x + threadIdx.x) >> 5;
    if (node >= N_NODES) return;
    int lane = threadIdx.x & 31;
    const float4* Zv = reinterpret_cast<const float4*>(Z);
    float4 acc = Zv[node * 32 + lane];
    int cnt = g_count[node];
    int deg = cnt < CAP ? cnt : CAP;
    const int4* sv = reinterpret_cast<const int4*>(&g_slot[node * CAP]);
    int nq = deg >> 2;

    float4 a1 = make_float4(0.f, 0.f, 0.f, 0.f);
    int4 cur = make_int4(0, 0, 0, 0);
    if (nq > 0) cur = sv[0];
    for (int q = 0; q < nq; q++) {
        int4 nxt = make_int4(0, 0, 0, 0);
        if (q + 1 < nq) nxt = sv[q + 1];          // prefetch next quad
        float4 v0 = Zv[cur.x * 32 + lane];
        float4 v1 = Zv[cur.y * 32 + lane];
        float4 v2 = Zv[cur.z * 32 + lane];
        float4 v3 = Zv[cur.w * 32 + lane];
        acc.x += v0.x + v2.x; acc.y += v0.y + v2.y;
        acc.z += v0.z + v2.z; acc.w += v0.w + v2.w;
        a1.x  += v1.x + v3.x; a1.y  += v1.y + v3.y;
        a1.z  += v1.z + v3.z; a1.w  += v1.w + v3.w;
        cur = nxt;
    }
    acc.x += a1.x; acc.y += a1.y; acc.z += a1.z; acc.w += a1.w;
    const int* sl = &g_slot[node * CAP];
    for (int j = nq << 2; j < deg; j++) {
        int s = sl[j];
        float4 v = Zv[s * 32 + lane];
        acc.x += v.x; acc.y += v.y; acc.z += v.z; acc.w += v.w;
    }

    float sc = 1.0f / ((float)cnt + 1.0f);
    float4 o = make_float4(fmaxf(acc.x * sc, 0.f), fmaxf(acc.y * sc, 0.f),
                           fmaxf(acc.z * sc, 0.f), fmaxf(acc.w * sc, 0.f));
    reinterpret_cast<float4*>(H)[node * 32 + lane] = o;
}

// Final layer: 64-dim, fp32 output.
__global__ void agg64_kernel(const float* __restrict__ Z,
                             float* __restrict__ out) {
    int node = (blockIdx.x * blockDim.x + threadIdx.x) >> 5;
    if (node >= N_NODES) return;
    int lane = threadIdx.x & 31;
    const float2* Zv = reinterpret_cast<const float2*>(Z);
    float2 acc = Zv[node * 32 + lane];
    int cnt = g_count[node];
    int deg = cnt < CAP ? cnt : CAP;
    const int4* sv = reinterpret_cast<const int4*>(&g_slot[node * CAP]);
    int nq = deg >> 2;

    float2 a1 = make_float2(0.f, 0.f);
    int4 cur = make_int4(0, 0, 0, 0);
    if (nq > 0) cur = sv[0];
    for (int q = 0; q < nq; q++) {
        int4 nxt = make_int4(0, 0, 0, 0);
        if (q + 1 < nq) nxt = sv[q + 1];
        float2 v0 = Zv[cur.x * 32 + lane];
        float2 v1 = Zv[cur.y * 32 + lane];
        float2 v2 = Zv[cur.z * 32 + lane];
        float2 v3 = Zv[cur.w * 32 + lane];
        acc.x += v0.x + v2.x; acc.y += v0.y + v2.y;
        a1.x  += v1.x + v3.x; a1.y  += v1.y + v3.y;
        cur = nxt;
    }
    acc.x += a1.x; acc.y += a1.y;
    const int* sl = &g_slot[node * CAP];
    for (int j = nq << 2; j < deg; j++) {
        int s = sl[j];
        float2 v = Zv[s * 32 + lane];
        acc.x += v.x; acc.y += v.y;
    }

    float sc = 1.0f / ((float)cnt + 1.0f);
    float2 o = make_float2(fmaxf(acc.x * sc, 0.f), fmaxf(acc.y * sc, 0.f));
    reinterpret_cast<float2*>(out)[node * 32 + lane] = o;
}

// ---------------- launch ----------------
extern "C" void kernel_launch(void* const* d_in, const int* in_sizes, int n_in,
                              void* d_out, int out_size) {
    const float* x   = (const float*)d_in[0];
    const int*   ei  = (const int*)d_in[1];
    const float* W1  = (const float*)d_in[2];
    const float* W2  = (const float*)d_in[3];
    const float* W3  = (const float*)d_in[4];
    float*       out = (float*)d_out;

    const int* src = ei;
    const int* dst = ei + N_EDGES;

    float* z  = nullptr;
    float* h  = nullptr;
    uint2* wp = nullptr;
    cudaGetSymbolAddress((void**)&z,  g_z);
    cudaGetSymbolAddress((void**)&h,  g_h);
    cudaGetSymbolAddress((void**)&wp, g_wp);

    constexpr int SMEM_A = 2 * 128 * 136 * 2;   // 69632 bytes
    cudaFuncSetAttribute(mma_gemm<128>, cudaFuncAttributeMaxDynamicSharedMemorySize, SMEM_A);
    cudaFuncSetAttribute(mma_gemm<64>,  cudaFuncAttributeMaxDynamicSharedMemorySize, SMEM_A);

    const int TPB = 256;
    const int gemm_blocks = (N_NODES + 127) / 128;           // 391
    const int agg_blocks  = (N_NODES * 32 + TPB - 1) / TPB;  // 6250

    // setup (zero counters + split/pack weights), adjacency buckets
    setup_kernel<<<(N_NODES + TPB - 1) / TPB, TPB>>>(W1, W2, W3);
    fill_kernel<<<(N_EDGES + TPB - 1) / TPB, TPB>>>(src, dst);

    // layer 1
    mma_gemm<128><<<gemm_blocks, 128, SMEM_A>>>(x, wp, z);
    agg128_kernel<<<agg_blocks, TPB>>>(z, h);
    // layer 2
    mma_gemm<128><<<gemm_blocks, 128, SMEM_A>>>(h, wp + 8192, z);
    agg128_kernel<<<agg_blocks, TPB>>>(z, h);
    // layer 3 (N=64), final relu + write out
    mma_gemm<64><<<gemm_blocks, 128, SMEM_A>>>(h, wp + 16384, z);
    agg64_kernel<<<agg_blocks, TPB>>>(z, out);
}

// round 7
// speedup vs baseline: 1.3358x; 1.0907x over previous
#include <cuda_runtime.h>
#include <cuda_bf16.h>
#include <cuda_fp16.h>
#include <cstdint>

#define N_NODES 50000
#define N_EDGES 800000
#define CAP 64

// ---------------- scratch (device globals; no allocation allowed) ----------
__device__ int    g_count[N_NODES];           // zero-init; re-zeroed by agg64
__device__ int    g_slot[N_NODES * CAP];
__device__ __half g_zh[N_NODES * 128];        // GEMM output, fp16
__device__ float  g_h[N_NODES * 128];         // agg output, fp32
// packed split weights: per (n, k-pair): {hi[k],hi[k+1]} , {lo[k],lo[k+1]}
// W1: 8192 uint2 | W2: 8192 | W3: 4096
__device__ uint2  g_wp[20480];

// ---------------- small helpers ----------------
__device__ __forceinline__ uint32_t smem_u32(const void* p) {
    uint32_t a;
    asm("{ .reg .u64 t; cvta.to.shared.u64 t, %1; cvt.u32.u64 %0, t; }"
        : "=r"(a) : "l"(p));
    return a;
}

#define LDMATRIX_X4(r, addr) \
    asm volatile("ldmatrix.sync.aligned.m8n8.x4.shared.b16 {%0,%1,%2,%3}, [%4];" \
                 : "=r"((r)[0]), "=r"((r)[1]), "=r"((r)[2]), "=r"((r)[3]) \
                 : "r"(addr))

#define MMA_BF16(acc, a, b0, b1) \
    asm volatile("mma.sync.aligned.m16n8k16.row.col.f32.bf16.bf16.f32 " \
                 "{%0,%1,%2,%3}, {%4,%5,%6,%7}, {%8,%9}, {%0,%1,%2,%3};" \
                 : "+f"((acc)[0]), "+f"((acc)[1]), "+f"((acc)[2]), "+f"((acc)[3]) \
                 : "r"((a)[0]), "r"((a)[1]), "r"((a)[2]), "r"((a)[3]), \
                   "r"(b0), "r"(b1))

__device__ __forceinline__ uint32_t pack_bf162(float a, float b) {
    __nv_bfloat162 p;
    p.x = __float2bfloat16_rn(a);
    p.y = __float2bfloat16_rn(b);
    return *reinterpret_cast<uint32_t*>(&p);
}

// accumulate 8 fp16 values (as uint4) into 8 fp32 accumulators
__device__ __forceinline__ void add8h(float* acc, uint4 v) {
    const __half2* h = reinterpret_cast<const __half2*>(&v);
    #pragma unroll
    for (int i = 0; i < 4; i++) {
        float2 f = __half22float2(h[i]);
        acc[2 * i]     += f.x;
        acc[2 * i + 1] += f.y;
    }
}

// ---------------- setup: build packed split-W (counts zeroed by agg64) -----
__global__ void setup_kernel(const float* __restrict__ W1,
                             const float* __restrict__ W2,
                             const float* __restrict__ W3) {
    int i = blockIdx.x * blockDim.x + threadIdx.x;
    if (i >= 20480) return;
    const float* W;
    int rel;
    if (i < 8192)       { W = W1; rel = i; }
    else if (i < 16384) { W = W2; rel = i - 8192; }
    else                { W = W3; rel = i - 16384; }
    int n  = rel >> 6;
    int kp = rel & 63;
    float v0 = W[n * 128 + kp * 2 + 0];
    float v1 = W[n * 128 + kp * 2 + 1];
    __nv_bfloat16 h0 = __float2bfloat16_rn(v0);
    __nv_bfloat16 h1 = __float2bfloat16_rn(v1);
    float l0 = v0 - __bfloat162float(h0);
    float l1 = v1 - __bfloat162float(h1);
    __nv_bfloat162 hi; hi.x = h0; hi.y = h1;
    uint2 out;
    out.x = *reinterpret_cast<uint32_t*>(&hi);
    out.y = pack_bf162(l0, l1);
    g_wp[i] = out;
}

// ---------------- bucket adjacency build ----------------
__global__ void fill_kernel(const int* __restrict__ src,
                            const int* __restrict__ dst) {
    int e = blockIdx.x * blockDim.x + threadIdx.x;
    if (e < N_EDGES) {
        int d = dst[e];
        int p = atomicAdd(&g_count[d], 1);
        if (p < CAP) g_slot[d * CAP + p] = src[e];
    }
}

// ---------------- mma.sync split-bf16 GEMM: Zh[128-tile][N] = A @ W^T ------
// A: [N_NODES,128] fp32 row-major; split to bf16 hi/lo during smem staging.
// Wp: packed split weights. D = Ahi*Whi^T + Ahi*Wlo^T + Alo*Whi^T (fp32 acc).
// Output written as fp16. 128 threads = 4 warps; warp owns 32 rows.
template <int N>
__global__ void __launch_bounds__(128, 2) mma_gemm(
    const float* __restrict__ A, const uint2* __restrict__ Wp,
    __half* __restrict__ Zh) {
    constexpr int NT  = N / 8;
    constexpr int LDA = 136;

    extern __shared__ __nv_bfloat16 smem[];
    __nv_bfloat16* Ash = smem;
    __nv_bfloat16* Asl = smem + 128 * LDA;

    const int tid  = threadIdx.x;
    const int wid  = tid >> 5;
    const int lane = tid & 31;
    const int m0   = blockIdx.x * 128;

    for (int t = tid; t < 4096; t += 128) {
        int r = t >> 5;
        int c = (t & 31) << 2;
        int m = m0 + r;
        float4 v = make_float4(0.f, 0.f, 0.f, 0.f);
        if (m < N_NODES)
            v = *reinterpret_cast<const float4*>(A + (size_t)m * 128 + c);
        __nv_bfloat16 h0 = __float2bfloat16_rn(v.x);
        __nv_bfloat16 h1 = __float2bfloat16_rn(v.y);
        __nv_bfloat16 h2 = __float2bfloat16_rn(v.z);
        __nv_bfloat16 h3 = __float2bfloat16_rn(v.w);
        __nv_bfloat162 hp0; hp0.x = h0; hp0.y = h1;
        __nv_bfloat162 hp1; hp1.x = h2; hp1.y = h3;
        uint2 hv, lv;
        hv.x = *reinterpret_cast<uint32_t*>(&hp0);
        hv.y = *reinterpret_cast<uint32_t*>(&hp1);
        lv.x = pack_bf162(v.x - __bfloat162float(h0), v.y - __bfloat162float(h1));
        lv.y = pack_bf162(v.z - __bfloat162float(h2), v.w - __bfloat162float(h3));
        *reinterpret_cast<uint2*>(Ash + r * LDA + c) = hv;
        *reinterpret_cast<uint2*>(Asl + r * LDA + c) = lv;
    }
    __syncthreads();

    float acc[2][NT][4];
    #pragma unroll
    for (int mt = 0; mt < 2; mt++)
        #pragma unroll
        for (int nt = 0; nt < NT; nt++)
            #pragma unroll
            for (int i = 0; i < 4; i++) acc[mt][nt][i] = 0.0f;

    const int wrow = wid * 32;
    const int lrow = lane & 15;
    const int kgrp = (lane >> 4) * 8;
    const int wn   = lane >> 2;
    const int wkp  = lane & 3;

    #pragma unroll
    for (int ks = 0; ks < 8; ks++) {
        const int k0 = ks * 16;
        uint32_t ah[2][4], al[2][4];
        #pragma unroll
        for (int mt = 0; mt < 2; mt++) {
            uint32_t ad = smem_u32(Ash + (wrow + mt * 16 + lrow) * LDA + k0 + kgrp);
            LDMATRIX_X4(ah[mt], ad);
            uint32_t bd = smem_u32(Asl + (wrow + mt * 16 + lrow) * LDA + k0 + kgrp);
            LDMATRIX_X4(al[mt], bd);
        }
        #pragma unroll
        for (int nt = 0; nt < NT; nt++) {
            const uint2* wp = Wp + (size_t)(nt * 8 + wn) * 64 + (k0 >> 1) + wkp;
            uint2 p0 = wp[0];
            uint2 p1 = wp[4];
            #pragma unroll
            for (int mt = 0; mt < 2; mt++) {
                MMA_BF16(acc[mt][nt], ah[mt], p0.x, p1.x);
                MMA_BF16(acc[mt][nt], ah[mt], p0.y, p1.y);
                MMA_BF16(acc[mt][nt], al[mt], p0.x, p1.x);
            }
        }
    }

    // epilogue -> fp16
    #pragma unroll
    for (int mt = 0; mt < 2; mt++) {
        int r0 = m0 + wrow + mt * 16 + (lane >> 2);
        #pragma unroll
        for (int nt = 0; nt < NT; nt++) {
            int col = nt * 8 + (lane & 3) * 2;
            if (r0 < N_NODES) {
                __half2 hv = __floats2half2_rn(acc[mt][nt][0], acc[mt][nt][1]);
                *reinterpret_cast<__half2*>(Zh + (size_t)r0 * N + col) = hv;
            }
            if (r0 + 8 < N_NODES) {
                __half2 hv = __floats2half2_rn(acc[mt][nt][2], acc[mt][nt][3]);
                *reinterpret_cast<__half2*>(Zh + (size_t)(r0 + 8) * N + col) = hv;
            }
        }
    }
}

// ---------------- gather + self + inv-scale + relu (fp16 z) ----------------
// Warp = 2 groups of 16 lanes; each group gathers one neighbor row per
// iteration (16 lanes x 16B = full 256B fp16 row). Partials merged with
// 8 shfls once per node. Output H fp32.
__global__ void agg128_kernel(const __half* __restrict__ Z,
                              float* __restrict__ H) {
    int node = (blockIdx.x * blockDim.x + threadIdx.x) >> 5;
    if (node >= N_NODES) return;
    int lane = threadIdx.x & 31;
    int g = lane >> 4;        // group 0/1
    int c = lane & 15;        // col-group: cols c*8 .. c*8+7

    float acc[8];
    #pragma unroll
    for (int i = 0; i < 8; i++) acc[i] = 0.f;

    // self term (group 0 only)
    if (g == 0) {
        uint4 v = *reinterpret_cast<const uint4*>(Z + (size_t)node * 128 + c * 8);
        add8h(acc, v);
    }

    int cnt = g_count[node];
    int deg = cnt < CAP ? cnt : CAP;
    const int* sl = &g_slot[node * CAP];

    int j = g;
    int idx = (j < deg) ? sl[j] : 0;
    while (j < deg) {
        int jn = j + 2;
        int idxn = (jn < deg) ? sl[jn] : 0;     // prefetch next index
        uint4 v = *reinterpret_cast<const uint4*>(Z + (size_t)idx * 128 + c * 8);
        add8h(acc, v);
        j = jn; idx = idxn;
    }

    __syncwarp();
    #pragma unroll
    for (int i = 0; i < 8; i++)
        acc[i] += __shfl_down_sync(0xffffffffu, acc[i], 16);

    if (g == 0) {
        float sc = 1.0f / ((float)cnt + 1.0f);
        float4 o0 = make_float4(fmaxf(acc[0] * sc, 0.f), fmaxf(acc[1] * sc, 0.f),
                                fmaxf(acc[2] * sc, 0.f), fmaxf(acc[3] * sc, 0.f));
        float4 o1 = make_float4(fmaxf(acc[4] * sc, 0.f), fmaxf(acc[5] * sc, 0.f),
                                fmaxf(acc[6] * sc, 0.f), fmaxf(acc[7] * sc, 0.f));
        float4* dst = reinterpret_cast<float4*>(H + (size_t)node * 128 + c * 8);
        dst[0] = o0;
        dst[1] = o1;
    }
}

// Final layer: 64-dim fp16 z, fp32 output. Warp = 4 groups of 8 lanes.
// Also re-zeroes g_count for the next launch (replay determinism).
__global__ void agg64_kernel(const __half* __restrict__ Z,
                             float* __restrict__ out) {
    int node = (blockIdx.x * blockDim.x + threadIdx.x) >> 5;
    if (node >= N_NODES) return;
    int lane = threadIdx.x & 31;
    int g = lane >> 3;        // group 0..3
    int c = lane & 7;         // col-group: cols c*8 .. c*8+7

    float acc[8];
    #pragma unroll
    for (int i = 0; i < 8; i++) acc[i] = 0.f;

    if (g == 0) {
        uint4 v = *reinterpret_cast<const uint4*>(Z + (size_t)node * 64 + c * 8);
        add8h(acc, v);
    }

    int cnt = g_count[node];
    int deg = cnt < CAP ? cnt : CAP;
    const int* sl = &g_slot[node * CAP];

    int j = g;
    int idx = (j < deg) ? sl[j] : 0;
    while (j < deg) {
        int jn = j + 4;
        int idxn = (jn < deg) ? sl[jn] : 0;
        uint4 v = *reinterpret_cast<const uint4*>(Z + (size_t)idx * 64 + c * 8);
        add8h(acc, v);
        j = jn; idx = idxn;
    }

    __syncwarp();
    #pragma unroll
    for (int i = 0; i < 8; i++)
        acc[i] += __shfl_down_sync(0xffffffffu, acc[i], 16);
    #pragma unroll
    for (int i = 0; i < 8; i++)
        acc[i] += __shfl_down_sync(0xffffffffu, acc[i], 8);

    if (lane < 8) {
        float sc = 1.0f / ((float)cnt + 1.0f);
        float4 o0 = make_float4(fmaxf(acc[0] * sc, 0.f), fmaxf(acc[1] * sc, 0.f),
                                fmaxf(acc[2] * sc, 0.f), fmaxf(acc[3] * sc, 0.f));
        float4 o1 = make_float4(fmaxf(acc[4] * sc, 0.f), fmaxf(acc[5] * sc, 0.f),
                                fmaxf(acc[6] * sc, 0.f), fmaxf(acc[7] * sc, 0.f));
        float4* dst = reinterpret_cast<float4*>(out + (size_t)node * 64 + c * 8);
        dst[0] = o0;
        dst[1] = o1;
    }
    if (lane == 0) g_count[node] = 0;   // reset for next launch / replay
}

// ---------------- launch ----------------
extern "C" void kernel_launch(void* const* d_in, const int* in_sizes, int n_in,
                              void* d_out, int out_size) {
    const float* x   = (const float*)d_in[0];
    const int*   ei  = (const int*)d_in[1];
    const float* W1  = (const float*)d_in[2];
    const float* W2  = (const float*)d_in[3];
    const float* W3  = (const float*)d_in[4];
    float*       out = (float*)d_out;

    const int* src = ei;
    const int* dst = ei + N_EDGES;

    __half* zh = nullptr;
    float*  h  = nullptr;
    uint2*  wp = nullptr;
    cudaGetSymbolAddress((void**)&zh, g_zh);
    cudaGetSymbolAddress((void**)&h,  g_h);
    cudaGetSymbolAddress((void**)&wp, g_wp);

    constexpr int SMEM_A = 2 * 128 * 136 * 2;   // 69632 bytes
    cudaFuncSetAttribute(mma_gemm<128>, cudaFuncAttributeMaxDynamicSharedMemorySize, SMEM_A);
    cudaFuncSetAttribute(mma_gemm<64>,  cudaFuncAttributeMaxDynamicSharedMemorySize, SMEM_A);

    const int TPB = 256;
    const int gemm_blocks = (N_NODES + 127) / 128;           // 391
    const int agg_blocks  = (N_NODES * 32 + TPB - 1) / TPB;  // 6250

    setup_kernel<<<80, TPB>>>(W1, W2, W3);
    fill_kernel<<<(N_EDGES + TPB - 1) / TPB, TPB>>>(src, dst);

    // layer 1
    mma_gemm<128><<<gemm_blocks, 128, SMEM_A>>>(x, wp, zh);
    agg128_kernel<<<agg_blocks, TPB>>>(zh, h);
    // layer 2
    mma_gemm<128><<<gemm_blocks, 128, SMEM_A>>>(h, wp + 8192, zh);
    agg128_kernel<<<agg_blocks, TPB>>>(zh, h);
    // layer 3 (N=64), final relu + write out
    mma_gemm<64><<<gemm_blocks, 128, SMEM_A>>>(h, wp + 16384, zh);
    agg64_kernel<<<agg_blocks, TPB>>>(zh, out);
}